// round 5
// baseline (speedup 1.0000x reference)
#include <cuda_runtime.h>
#include <cuda_bf16.h>
#include <cstdint>
#include <cstddef>

// ============================================================================
// QLinear via int8 IMMA (mma.sync m16n8k32 s8.s8.s32) — exact integer math.
// w_s = max|W|/127; b_s = w_s*a_s; out = (x_int @ w_int^T + b_int) * b_s
// R4 resubmit (R4 bench was an infra failure, not a kernel failure):
//   BM=256/512thr GEMM, 4-stage pipe, fused finalize+quantW+quantB,
//   widened streaming quant_x, init kernel dropped.
// ============================================================================

#define DEV_INLINE __device__ __forceinline__

namespace {
constexpr int NTOK = 32768;
constexpr int DIN  = 768;
constexpr int DOUT = 768;
constexpr long long NM = (long long)NTOK * DOUT;

constexpr int BM = 256;
constexpr int BN = 128;
constexpr int BK = 128;               // bytes of K per stage (int8)
constexpr int KT = DIN / BK;          // 6
constexpr int STAGES = 4;
constexpr int THREADS = 512;

constexpr int STRIDE = 144;           // 128B data + 16B pad: conflict-free ldmatrix
constexpr int A_BYTES = BM * STRIDE;  // 36864
constexpr int B_BYTES = BN * STRIDE;  // 18432
constexpr int STAGE_BYTES = A_BYTES + B_BYTES;        // 55296
constexpr int SMEM_BYTES  = STAGES * STAGE_BYTES;     // 221184
} // namespace

// ---------------- device scratch (static: no runtime allocation) ------------
__device__ __align__(16) int8_t g_xq[(size_t)NTOK * DIN]; // 25.2 MB
__device__ __align__(16) int8_t g_wq[(size_t)DOUT * DIN]; // 0.59 MB
__device__ __align__(16) float  g_bint[DOUT];
__device__ unsigned int g_wmax_bits;                      // zero-init; atomicMax idempotent
__device__ float g_bs;

// ---------------- PTX helpers ------------------------------------------------
DEV_INLINE uint32_t smem_u32(const void* p) {
    uint32_t a;
    asm("{ .reg .u64 t; cvta.to.shared.u64 t, %1; cvt.u32.u64 %0, t; }" : "=r"(a) : "l"(p));
    return a;
}

#define CP16(dst, src) \
    asm volatile("cp.async.cg.shared.global [%0], [%1], 16;" :: "r"(dst), "l"(src))
#define CP_COMMIT() asm volatile("cp.async.commit_group;" ::: "memory")
#define CP_WAIT(n)  asm volatile("cp.async.wait_group %0;" :: "n"(n) : "memory")

#define LDSM_X4(r, addr)                                                        \
    asm volatile("ldmatrix.sync.aligned.m8n8.x4.shared.b16 {%0,%1,%2,%3}, [%4];" \
        : "=r"((r)[0]), "=r"((r)[1]), "=r"((r)[2]), "=r"((r)[3]) : "r"(addr))

#define IMMA(d, a, b0, b1)                                                      \
    asm volatile("mma.sync.aligned.m16n8k32.row.col.s32.s8.s8.s32 "             \
        "{%0,%1,%2,%3}, {%4,%5,%6,%7}, {%8,%9}, {%0,%1,%2,%3};"                 \
        : "+r"((d)[0]), "+r"((d)[1]), "+r"((d)[2]), "+r"((d)[3])                \
        : "r"((a)[0]), "r"((a)[1]), "r"((a)[2]), "r"((a)[3]), "r"(b0), "r"(b1))

// ---------------- quant helpers ----------------------------------------------
DEV_INLINE float q8f(float x, float s) {
    return fminf(fmaxf(rintf(__fdiv_rn(x, s)), -128.f), 127.f);
}
DEV_INLINE uint32_t pack4(float a, float b, float c, float d) {
    return (uint32_t)((int)a & 0xff) | ((uint32_t)((int)b & 0xff) << 8) |
           ((uint32_t)((int)c & 0xff) << 16) | ((uint32_t)((int)d & 0xff) << 24);
}

// ---------------- small kernels ----------------------------------------------
__global__ void qlinear_wmax(const float* __restrict__ w) {
    float m = 0.f;
    const float4* w4 = reinterpret_cast<const float4*>(w);
    int n4 = (DOUT * DIN) >> 2;
    for (int j = blockIdx.x * blockDim.x + threadIdx.x; j < n4; j += gridDim.x * blockDim.x) {
        float4 v = w4[j];
        m = fmaxf(m, fmaxf(fmaxf(fabsf(v.x), fabsf(v.y)), fmaxf(fabsf(v.z), fabsf(v.w))));
    }
    #pragma unroll
    for (int o = 16; o; o >>= 1) m = fmaxf(m, __shfl_xor_sync(0xffffffffu, m, o));
    if ((threadIdx.x & 31) == 0) atomicMax(&g_wmax_bits, __float_as_uint(m));
}

// fused: finalize (g_bs + tail of out) + quantize W + quantize bias
__global__ void qlinear_prep(const float* __restrict__ w,
                             const float* __restrict__ bias,
                             const float* __restrict__ a_s,
                             float* __restrict__ out, long long out_size) {
    const float ws = __fdiv_rn(__uint_as_float(g_wmax_bits), 127.0f);
    const float bs = __fmul_rn(ws, a_s[0]);

    if (blockIdx.x == 0) {
        if (threadIdx.x == 0) g_bs = bs;
        for (long long i = NM + threadIdx.x; i < out_size; i += blockDim.x) out[i] = bs;
        for (int i = threadIdx.x; i < DOUT; i += blockDim.x) {
            float q = rintf(__fdiv_rn(bias[i], bs));
            g_bint[i] = fminf(fmaxf(q, -2147483648.f), 2147483648.f);
        }
    }

    const float4* w4 = reinterpret_cast<const float4*>(w);
    uint32_t* dst = reinterpret_cast<uint32_t*>(g_wq);
    int n4 = (DOUT * DIN) >> 2;
    for (int j = blockIdx.x * blockDim.x + threadIdx.x; j < n4; j += gridDim.x * blockDim.x) {
        float4 v = w4[j];
        dst[j] = pack4(q8f(v.x, ws), q8f(v.y, ws), q8f(v.z, ws), q8f(v.w, ws));
    }
}

// quant_x: 4x float4 in (streaming), one uint4 out per thread
__global__ void qlinear_quant_x(const float* __restrict__ x, const float* __restrict__ a_s) {
    const float s = a_s[0];
    const float4* x4 = reinterpret_cast<const float4*>(x);
    uint4* dst = reinterpret_cast<uint4*>(g_xq);
    int n16 = (NTOK * DIN) >> 4;
    for (int j = blockIdx.x * blockDim.x + threadIdx.x; j < n16; j += gridDim.x * blockDim.x) {
        float4 v0 = __ldcs(&x4[j * 4 + 0]);
        float4 v1 = __ldcs(&x4[j * 4 + 1]);
        float4 v2 = __ldcs(&x4[j * 4 + 2]);
        float4 v3 = __ldcs(&x4[j * 4 + 3]);
        uint4 p;
        p.x = pack4(q8f(v0.x, s), q8f(v0.y, s), q8f(v0.z, s), q8f(v0.w, s));
        p.y = pack4(q8f(v1.x, s), q8f(v1.y, s), q8f(v1.z, s), q8f(v1.w, s));
        p.z = pack4(q8f(v2.x, s), q8f(v2.y, s), q8f(v2.z, s), q8f(v2.w, s));
        p.w = pack4(q8f(v3.x, s), q8f(v3.y, s), q8f(v3.z, s), q8f(v3.w, s));
        dst[j] = p;
    }
}

// ---------------- GEMM -------------------------------------------------------
DEV_INLINE void load_stage(uint32_t sbase, const int8_t* gA, const int8_t* gB,
                           int kt, int tid) {
    const int kbase = kt * BK;
    #pragma unroll
    for (int j = 0; j < 4; j++) {          // A: 256 rows x 8 chunks of 16B = 2048
        int idx = tid + j * THREADS;
        int r = idx >> 3, c = idx & 7;
        CP16(sbase + r * STRIDE + c * 16, gA + (size_t)r * DIN + kbase + c * 16);
    }
    #pragma unroll
    for (int j = 0; j < 2; j++) {          // B: 128 rows x 8 chunks of 16B = 1024
        int idx = tid + j * THREADS;
        int r = idx >> 3, c = idx & 7;
        CP16(sbase + A_BYTES + r * STRIDE + c * 16, gB + (size_t)r * DIN + kbase + c * 16);
    }
    CP_COMMIT();
}

__global__ __launch_bounds__(THREADS) void qlinear_gemm(float* __restrict__ out) {
    extern __shared__ char smem_raw[];
    const uint32_t sb = smem_u32(smem_raw);
    const int tid  = threadIdx.x;
    const int lane = tid & 31;
    const int wid  = tid >> 5;
    const int warp_m = wid & 7;            // 8 warps over M (32 rows each)
    const int warp_n = wid >> 3;           // 2 warps over N (64 cols each)
    const int m0 = blockIdx.y * BM;
    const int n0 = blockIdx.x * BN;

    const int8_t* gA = g_xq + (size_t)m0 * DIN;
    const int8_t* gB = g_wq + (size_t)n0 * DIN;

    // prologue: fill stages 0..2
    load_stage(sb + 0 * STAGE_BYTES, gA, gB, 0, tid);
    load_stage(sb + 1 * STAGE_BYTES, gA, gB, 1, tid);
    load_stage(sb + 2 * STAGE_BYTES, gA, gB, 2, tid);

    int acc[2][8][4];
    #pragma unroll
    for (int mi = 0; mi < 2; mi++)
        #pragma unroll
        for (int na = 0; na < 8; na++)
            #pragma unroll
            for (int q = 0; q < 4; q++) acc[mi][na][q] = 0;

    const uint32_t lmA = (uint32_t)(warp_m * 32 + (lane & 15)) * STRIDE + (lane & 16);
    const uint32_t lmB = (uint32_t)(warp_n * 64 + (lane & 15)) * STRIDE + (lane & 16);

    for (int kt = 0; kt < KT; kt++) {
        const int slot = kt & (STAGES - 1);
        int allowed = KT - 1 - kt;
        if (allowed > STAGES - 2) allowed = STAGES - 2;
        switch (allowed) { case 0: CP_WAIT(0); break; case 1: CP_WAIT(1); break; default: CP_WAIT(2); break; }
        __syncthreads();

        if (kt + STAGES - 1 < KT)
            load_stage(sb + ((kt + STAGES - 1) & (STAGES - 1)) * STAGE_BYTES,
                       gA, gB, kt + STAGES - 1, tid);

        const uint32_t aBase = sb + slot * STAGE_BYTES + lmA;
        const uint32_t bBase = sb + slot * STAGE_BYTES + A_BYTES + lmB;

        #pragma unroll
        for (int ks = 0; ks < 4; ks++) {   // 4 x k32 per 128B stage
            uint32_t af[2][4];
            #pragma unroll
            for (int mi = 0; mi < 2; mi++)
                LDSM_X4(af[mi], aBase + mi * 16 * STRIDE + ks * 32);
            uint32_t bf[4][4];
            #pragma unroll
            for (int nj = 0; nj < 4; nj++)
                LDSM_X4(bf[nj], bBase + nj * 16 * STRIDE + ks * 32);
            #pragma unroll
            for (int mi = 0; mi < 2; mi++)
                #pragma unroll
                for (int na = 0; na < 8; na++) {
                    const int nj = na >> 1, hi = na & 1;
                    IMMA(acc[mi][na], af[mi], bf[nj][hi], bf[nj][hi + 2]);
                }
        }
    }

    // epilogue: (acc + b_int) * b_s, direct float2 global stores (exact math)
    const float bs = g_bs;
    const int g = lane >> 2, tig = lane & 3;
    #pragma unroll
    for (int mi = 0; mi < 2; mi++) {
        #pragma unroll
        for (int na = 0; na < 8; na++) {
            const int row = m0 + warp_m * 32 + mi * 16 + g;
            const int col = n0 + warp_n * 64 + na * 8 + 2 * tig;
            const float2 bi = *reinterpret_cast<const float2*>(&g_bint[col]);
            float2 v0, v1;
            v0.x = (__int2float_rn(acc[mi][na][0]) + bi.x) * bs;
            v0.y = (__int2float_rn(acc[mi][na][1]) + bi.y) * bs;
            v1.x = (__int2float_rn(acc[mi][na][2]) + bi.x) * bs;
            v1.y = (__int2float_rn(acc[mi][na][3]) + bi.y) * bs;
            *reinterpret_cast<float2*>(&out[(size_t)row * DOUT + col]) = v0;
            *reinterpret_cast<float2*>(&out[(size_t)(row + 8) * DOUT + col]) = v1;
        }
    }
}

// ---------------- launch -----------------------------------------------------
extern "C" void kernel_launch(void* const* d_in, const int* in_sizes, int n_in,
                              void* d_out, int out_size) {
    const float *x = nullptr, *a_s = nullptr, *w = nullptr, *bias = nullptr;
    for (int i = 0; i < n_in; i++) {
        if      (in_sizes[i] == NTOK * DIN) x    = (const float*)d_in[i];
        else if (in_sizes[i] == 1)          a_s  = (const float*)d_in[i];
        else if (in_sizes[i] == DOUT * DIN) w    = (const float*)d_in[i];
        else if (in_sizes[i] == DOUT)       bias = (const float*)d_in[i];
    }
    float* out = (float*)d_out;

    cudaFuncSetAttribute(qlinear_gemm, cudaFuncAttributeMaxDynamicSharedMemorySize, SMEM_BYTES);

    qlinear_wmax<<<1184, 256>>>(w);
    qlinear_prep<<<576, 256>>>(w, bias, a_s, out, (long long)out_size);
    qlinear_quant_x<<<3072, 512>>>(x, a_s);

    dim3 grid(DOUT / BN, NTOK / BM);   // (6, 128) = 768 CTAs
    qlinear_gemm<<<grid, THREADS, SMEM_BYTES>>>(out);
}

// round 6
// speedup vs baseline: 1.2288x; 1.2288x over previous
#include <cuda_runtime.h>
#include <cuda_bf16.h>
#include <cstdint>
#include <cstddef>

// ============================================================================
// QLinear via int8 IMMA (mma.sync m16n8k32 s8.s8.s32) — exact integer math.
// w_s = max|W|/127; b_s = w_s*a_s; out = (x_int @ w_int^T + b_int) * b_s
// R6: 2 CTAs/SM (XOR-swizzled 128B-stride smem, 96KB/CTA, launch_bounds(256,2))
//     to overlap barrier/wait stalls across CTAs. GEMM profile R5: tensor 34%,
//     issue 25%, occ 24% -> stall-bound at 1 CTA/SM.
// ============================================================================

#define DEV_INLINE __device__ __forceinline__

namespace {
constexpr int NTOK = 32768;
constexpr int DIN  = 768;
constexpr int DOUT = 768;
constexpr long long NM = (long long)NTOK * DOUT;

constexpr int BM = 128;
constexpr int BN = 128;
constexpr int BK = 128;               // bytes of K per stage (int8)
constexpr int KT = DIN / BK;          // 6
constexpr int STAGES = 3;
constexpr int THREADS = 256;

constexpr int A_BYTES = BM * 128;     // 16384 (no pad; XOR swizzle)
constexpr int B_BYTES = BN * 128;     // 16384
constexpr int STAGE_BYTES = A_BYTES + B_BYTES;        // 32768
constexpr int SMEM_BYTES  = STAGES * STAGE_BYTES;     // 98304 -> 2 CTAs/SM
} // namespace

// ---------------- device scratch (static: no runtime allocation) ------------
__device__ __align__(16) int8_t g_xq[(size_t)NTOK * DIN]; // 25.2 MB
__device__ __align__(16) int8_t g_wq[(size_t)DOUT * DIN]; // 0.59 MB
__device__ __align__(16) float  g_bint[DOUT];
__device__ unsigned int g_wmax_bits;                      // zero-init; atomicMax idempotent
__device__ float g_bs;

// ---------------- PTX helpers ------------------------------------------------
DEV_INLINE uint32_t smem_u32(const void* p) {
    uint32_t a;
    asm("{ .reg .u64 t; cvta.to.shared.u64 t, %1; cvt.u32.u64 %0, t; }" : "=r"(a) : "l"(p));
    return a;
}

#define CP16(dst, src) \
    asm volatile("cp.async.cg.shared.global [%0], [%1], 16;" :: "r"(dst), "l"(src))
#define CP_COMMIT() asm volatile("cp.async.commit_group;" ::: "memory")
#define CP_WAIT(n)  asm volatile("cp.async.wait_group %0;" :: "n"(n) : "memory")

#define LDSM_X4(r, addr)                                                        \
    asm volatile("ldmatrix.sync.aligned.m8n8.x4.shared.b16 {%0,%1,%2,%3}, [%4];" \
        : "=r"((r)[0]), "=r"((r)[1]), "=r"((r)[2]), "=r"((r)[3]) : "r"(addr))

#define IMMA(d, a, b0, b1)                                                      \
    asm volatile("mma.sync.aligned.m16n8k32.row.col.s32.s8.s8.s32 "             \
        "{%0,%1,%2,%3}, {%4,%5,%6,%7}, {%8,%9}, {%0,%1,%2,%3};"                 \
        : "+r"((d)[0]), "+r"((d)[1]), "+r"((d)[2]), "+r"((d)[3])                \
        : "r"((a)[0]), "r"((a)[1]), "r"((a)[2]), "r"((a)[3]), "r"(b0), "r"(b1))

// ---------------- quant helpers ----------------------------------------------
DEV_INLINE float q8f(float x, float s) {
    return fminf(fmaxf(rintf(__fdiv_rn(x, s)), -128.f), 127.f);
}
DEV_INLINE uint32_t pack4(float a, float b, float c, float d) {
    return (uint32_t)((int)a & 0xff) | ((uint32_t)((int)b & 0xff) << 8) |
           ((uint32_t)((int)c & 0xff) << 16) | ((uint32_t)((int)d & 0xff) << 24);
}

// ---------------- small kernels ----------------------------------------------
__global__ void qlinear_wmax(const float* __restrict__ w) {
    float m = 0.f;
    const float4* w4 = reinterpret_cast<const float4*>(w);
    int n4 = (DOUT * DIN) >> 2;
    for (int j = blockIdx.x * blockDim.x + threadIdx.x; j < n4; j += gridDim.x * blockDim.x) {
        float4 v = w4[j];
        m = fmaxf(m, fmaxf(fmaxf(fabsf(v.x), fabsf(v.y)), fmaxf(fabsf(v.z), fabsf(v.w))));
    }
    #pragma unroll
    for (int o = 16; o; o >>= 1) m = fmaxf(m, __shfl_xor_sync(0xffffffffu, m, o));
    if ((threadIdx.x & 31) == 0) atomicMax(&g_wmax_bits, __float_as_uint(m));
}

// fused: finalize (g_bs + tail of out) + quantize W + quantize bias
__global__ void qlinear_prep(const float* __restrict__ w,
                             const float* __restrict__ bias,
                             const float* __restrict__ a_s,
                             float* __restrict__ out, long long out_size) {
    const float ws = __fdiv_rn(__uint_as_float(g_wmax_bits), 127.0f);
    const float bs = __fmul_rn(ws, a_s[0]);

    if (blockIdx.x == 0) {
        if (threadIdx.x == 0) g_bs = bs;
        for (long long i = NM + threadIdx.x; i < out_size; i += blockDim.x) out[i] = bs;
        for (int i = threadIdx.x; i < DOUT; i += blockDim.x) {
            float q = rintf(__fdiv_rn(bias[i], bs));
            g_bint[i] = fminf(fmaxf(q, -2147483648.f), 2147483648.f);
        }
    }

    const float4* w4 = reinterpret_cast<const float4*>(w);
    uint32_t* dst = reinterpret_cast<uint32_t*>(g_wq);
    int n4 = (DOUT * DIN) >> 2;
    for (int j = blockIdx.x * blockDim.x + threadIdx.x; j < n4; j += gridDim.x * blockDim.x) {
        float4 v = w4[j];
        dst[j] = pack4(q8f(v.x, ws), q8f(v.y, ws), q8f(v.z, ws), q8f(v.w, ws));
    }
}

// quant_x: 4x float4 in (streaming), one uint4 out per thread
__global__ void qlinear_quant_x(const float* __restrict__ x, const float* __restrict__ a_s) {
    const float s = a_s[0];
    const float4* x4 = reinterpret_cast<const float4*>(x);
    uint4* dst = reinterpret_cast<uint4*>(g_xq);
    int n16 = (NTOK * DIN) >> 4;
    for (int j = blockIdx.x * blockDim.x + threadIdx.x; j < n16; j += gridDim.x * blockDim.x) {
        float4 v0 = __ldcs(&x4[j * 4 + 0]);
        float4 v1 = __ldcs(&x4[j * 4 + 1]);
        float4 v2 = __ldcs(&x4[j * 4 + 2]);
        float4 v3 = __ldcs(&x4[j * 4 + 3]);
        uint4 p;
        p.x = pack4(q8f(v0.x, s), q8f(v0.y, s), q8f(v0.z, s), q8f(v0.w, s));
        p.y = pack4(q8f(v1.x, s), q8f(v1.y, s), q8f(v1.z, s), q8f(v1.w, s));
        p.z = pack4(q8f(v2.x, s), q8f(v2.y, s), q8f(v2.z, s), q8f(v2.w, s));
        p.w = pack4(q8f(v3.x, s), q8f(v3.y, s), q8f(v3.z, s), q8f(v3.w, s));
        dst[j] = p;
    }
}

// ---------------- GEMM -------------------------------------------------------
// XOR swizzle: byte chunk c (16B units, 0..7 within a 128B row) -> c ^ (row&7).
DEV_INLINE uint32_t swz(uint32_t row, uint32_t c16) {
    return row * 128u + ((c16 ^ (row & 7u)) << 4);
}

DEV_INLINE void load_stage(uint32_t sbase, const int8_t* gA, const int8_t* gB,
                           int kt, int tid) {
    const int kbase = kt * BK;
    #pragma unroll
    for (int j = 0; j < 4; j++) {          // A: 128 rows x 8 chunks of 16B = 1024
        int idx = tid + j * THREADS;
        uint32_t r = idx >> 3, c = idx & 7;
        CP16(sbase + swz(r, c), gA + (size_t)r * DIN + kbase + c * 16);
    }
    #pragma unroll
    for (int j = 0; j < 4; j++) {          // B: 128 rows x 8 chunks of 16B = 1024
        int idx = tid + j * THREADS;
        uint32_t r = idx >> 3, c = idx & 7;
        CP16(sbase + A_BYTES + swz(r, c), gB + (size_t)r * DIN + kbase + c * 16);
    }
    CP_COMMIT();
}

__global__ __launch_bounds__(THREADS, 2) void qlinear_gemm(float* __restrict__ out) {
    extern __shared__ char smem_raw[];
    const uint32_t sb = smem_u32(smem_raw);
    const int tid  = threadIdx.x;
    const int lane = tid & 31;
    const int wid  = tid >> 5;
    const int warp_m = wid & 3;            // 4 warps over M (32 rows each)
    const int warp_n = wid >> 2;           // 2 warps over N (64 cols each)
    const int m0 = blockIdx.y * BM;
    const int n0 = blockIdx.x * BN;

    const int8_t* gA = g_xq + (size_t)m0 * DIN;
    const int8_t* gB = g_wq + (size_t)n0 * DIN;

    // prologue
    load_stage(sb + 0 * STAGE_BYTES, gA, gB, 0, tid);
    load_stage(sb + 1 * STAGE_BYTES, gA, gB, 1, tid);

    int acc[2][8][4];
    #pragma unroll
    for (int mi = 0; mi < 2; mi++)
        #pragma unroll
        for (int na = 0; na < 8; na++)
            #pragma unroll
            for (int q = 0; q < 4; q++) acc[mi][na][q] = 0;

    // ldmatrix per-lane addressing under XOR swizzle:
    // row = tileRowBase + (lane&15); chunk = 2*ks + ((lane>>4)&1), xor (lane&7)
    const uint32_t rA = (uint32_t)(warp_m * 32 + (lane & 15));
    const uint32_t rB = (uint32_t)(warp_n * 64 + (lane & 15));
    const uint32_t chalf = (uint32_t)((lane >> 4) & 1);
    const uint32_t r7 = (uint32_t)(lane & 7);

    for (int kt = 0; kt < KT; kt++) {
        const int slot = kt % STAGES;
        if (kt == KT - 1) { CP_WAIT(0); } else { CP_WAIT(1); }
        __syncthreads();

        if (kt + 2 < KT)
            load_stage(sb + ((kt + 2) % STAGES) * STAGE_BYTES, gA, gB, kt + 2, tid);

        const uint32_t aS = sb + slot * STAGE_BYTES;
        const uint32_t bS = aS + A_BYTES;

        #pragma unroll
        for (int ks = 0; ks < 4; ks++) {   // 4 x k32 per 128B stage
            const uint32_t swc = (((2u * ks + chalf) ^ r7) << 4);
            uint32_t af[2][4];
            #pragma unroll
            for (int mi = 0; mi < 2; mi++)
                LDSM_X4(af[mi], aS + (rA + mi * 16) * 128 + swc);
            uint32_t bf[4][4];
            #pragma unroll
            for (int nj = 0; nj < 4; nj++)
                LDSM_X4(bf[nj], bS + (rB + nj * 16) * 128 + swc);
            #pragma unroll
            for (int mi = 0; mi < 2; mi++)
                #pragma unroll
                for (int na = 0; na < 8; na++) {
                    const int nj = na >> 1, hi = na & 1;
                    IMMA(acc[mi][na], af[mi], bf[nj][hi], bf[nj][hi + 2]);
                }
        }
    }

    // epilogue: (acc + b_int) * b_s, direct float2 global stores (exact math)
    const float bs = g_bs;
    const int g = lane >> 2, tig = lane & 3;
    #pragma unroll
    for (int mi = 0; mi < 2; mi++) {
        #pragma unroll
        for (int na = 0; na < 8; na++) {
            const int row = m0 + warp_m * 32 + mi * 16 + g;
            const int col = n0 + warp_n * 64 + na * 8 + 2 * tig;
            const float2 bi = *reinterpret_cast<const float2*>(&g_bint[col]);
            float2 v0, v1;
            v0.x = (__int2float_rn(acc[mi][na][0]) + bi.x) * bs;
            v0.y = (__int2float_rn(acc[mi][na][1]) + bi.y) * bs;
            v1.x = (__int2float_rn(acc[mi][na][2]) + bi.x) * bs;
            v1.y = (__int2float_rn(acc[mi][na][3]) + bi.y) * bs;
            *reinterpret_cast<float2*>(&out[(size_t)row * DOUT + col]) = v0;
            *reinterpret_cast<float2*>(&out[(size_t)(row + 8) * DOUT + col]) = v1;
        }
    }
}

// ---------------- launch -----------------------------------------------------
extern "C" void kernel_launch(void* const* d_in, const int* in_sizes, int n_in,
                              void* d_out, int out_size) {
    const float *x = nullptr, *a_s = nullptr, *w = nullptr, *bias = nullptr;
    for (int i = 0; i < n_in; i++) {
        if      (in_sizes[i] == NTOK * DIN) x    = (const float*)d_in[i];
        else if (in_sizes[i] == 1)          a_s  = (const float*)d_in[i];
        else if (in_sizes[i] == DOUT * DIN) w    = (const float*)d_in[i];
        else if (in_sizes[i] == DOUT)       bias = (const float*)d_in[i];
    }
    float* out = (float*)d_out;

    cudaFuncSetAttribute(qlinear_gemm, cudaFuncAttributeMaxDynamicSharedMemorySize, SMEM_BYTES);

    qlinear_wmax<<<1184, 256>>>(w);
    qlinear_prep<<<576, 256>>>(w, bias, a_s, out, (long long)out_size);
    qlinear_quant_x<<<3072, 512>>>(x, a_s);

    dim3 grid(DOUT / BN, NTOK / BM);   // (6, 256) = 1536 CTAs
    qlinear_gemm<<<grid, THREADS, SMEM_BYTES>>>(out);
}